// round 1
// baseline (speedup 1.0000x reference)
#include <cuda_runtime.h>
#include <math.h>
#include <math_constants.h>

#define BATCH 4096
#define POOL  1024
#define SEL   5
#define PLEN  5
#define DIM   768
#define EPS   1e-8f

// ---- scratch (device globals: no allocation allowed) ----
__device__ float g_dots[(size_t)BATCH * POOL];   // 16.8 MB
__device__ float g_kn[POOL];
__device__ int   g_topk[BATCH * SEL];

// ============================================================
// Kernel 1: key norms. One block (128 threads) per pool row.
// ============================================================
__global__ void knorm_kernel(const float* __restrict__ key) {
    const int p = blockIdx.x;
    const float* row = key + (size_t)p * DIM;
    float s = 0.f;
    for (int i = threadIdx.x; i < DIM; i += blockDim.x) {
        float v = row[i];
        s += v * v;
    }
    // warp reduce
    #pragma unroll
    for (int o = 16; o > 0; o >>= 1) s += __shfl_down_sync(0xFFFFFFFFu, s, o);
    __shared__ float ws[4];
    const int wid = threadIdx.x >> 5, lid = threadIdx.x & 31;
    if (lid == 0) ws[wid] = s;
    __syncthreads();
    if (threadIdx.x == 0) {
        float t = ws[0] + ws[1] + ws[2] + ws[3];
        g_kn[p] = sqrtf(t);
    }
}

// ============================================================
// Kernel 2: SGEMM dots[B,POOL] = query @ key^T
// 128x128 tile, BK=8, 256 threads, 8x8 per thread.
// ============================================================
__global__ __launch_bounds__(256, 2)
void gemm_kernel(const float* __restrict__ A, const float* __restrict__ Kp) {
    __shared__ float As[8][128];
    __shared__ float Bs[8][128];

    const int tid = threadIdx.x;
    const int bm = blockIdx.y * 128;
    const int bn = blockIdx.x * 128;
    const int ty = tid >> 4;          // 0..15, M direction
    const int tx = tid & 15;          // 0..15, N direction

    float acc[8][8];
    #pragma unroll
    for (int i = 0; i < 8; i++)
        #pragma unroll
        for (int j = 0; j < 8; j++) acc[i][j] = 0.f;

    const int lrow = tid >> 1;        // 0..127
    const int lcol = (tid & 1) * 4;   // 0 or 4
    const float* Aptr = A  + (size_t)(bm + lrow) * DIM + lcol;
    const float* Kptr = Kp + (size_t)(bn + lrow) * DIM + lcol;

    for (int k0 = 0; k0 < DIM; k0 += 8) {
        float4 av = *(const float4*)(Aptr + k0);
        float4 bv = *(const float4*)(Kptr + k0);
        As[lcol + 0][lrow] = av.x; As[lcol + 1][lrow] = av.y;
        As[lcol + 2][lrow] = av.z; As[lcol + 3][lrow] = av.w;
        Bs[lcol + 0][lrow] = bv.x; Bs[lcol + 1][lrow] = bv.y;
        Bs[lcol + 2][lrow] = bv.z; Bs[lcol + 3][lrow] = bv.w;
        __syncthreads();

        #pragma unroll
        for (int k = 0; k < 8; k++) {
            float ra[8], rb[8];
            #pragma unroll
            for (int i = 0; i < 8; i++) ra[i] = As[k][ty * 8 + i];
            #pragma unroll
            for (int j = 0; j < 8; j++) rb[j] = Bs[k][tx * 8 + j];
            #pragma unroll
            for (int i = 0; i < 8; i++)
                #pragma unroll
                for (int j = 0; j < 8; j++)
                    acc[i][j] = fmaf(ra[i], rb[j], acc[i][j]);
        }
        __syncthreads();
    }

    #pragma unroll
    for (int i = 0; i < 8; i++) {
        float* out = g_dots + (size_t)(bm + ty * 8 + i) * POOL + bn + tx * 8;
        *(float4*)(out)     = make_float4(acc[i][0], acc[i][1], acc[i][2], acc[i][3]);
        *(float4*)(out + 4) = make_float4(acc[i][4], acc[i][5], acc[i][6], acc[i][7]);
    }
}

// ============================================================
// Kernel 3: per-row query norm + match + top-5 (ascending, tie->lower idx)
// One block (256 threads) per batch row; 4 pool entries per thread.
// ============================================================
__global__ __launch_bounds__(256)
void topk_kernel(const float* __restrict__ query, float* __restrict__ sim_out) {
    const int b = blockIdx.x;
    const int tid = threadIdx.x;

    __shared__ float red[256];
    __shared__ int   redi[256];
    __shared__ float s_qn;

    // --- query norm ---
    float s = 0.f;
    const float* qrow = query + (size_t)b * DIM;
    for (int i = tid; i < DIM; i += 256) {
        float v = qrow[i];
        s += v * v;
    }
    #pragma unroll
    for (int o = 16; o > 0; o >>= 1) s += __shfl_down_sync(0xFFFFFFFFu, s, o);
    if ((tid & 31) == 0) red[tid >> 5] = s;
    __syncthreads();
    if (tid == 0) {
        float t = 0.f;
        for (int w = 0; w < 8; w++) t += red[w];
        s_qn = sqrtf(t);
    }
    __syncthreads();
    const float qn = s_qn;

    // --- load 4 match values per thread ---
    float mv[4];
    int   mi[4];
    #pragma unroll
    for (int j = 0; j < 4; j++) {
        int p = tid + j * 256;
        float d = g_dots[(size_t)b * POOL + p];
        float denom = fmaxf(qn * g_kn[p], EPS);
        mv[j] = 1.0f - d / denom;
        mi[j] = p;
    }

    // --- 5 rounds of block argmin with (value, index) tie-break ---
    for (int sel = 0; sel < SEL; sel++) {
        float bv = mv[0]; int bi = mi[0];
        #pragma unroll
        for (int j = 1; j < 4; j++) {
            if (mv[j] < bv || (mv[j] == bv && mi[j] < bi)) { bv = mv[j]; bi = mi[j]; }
        }
        red[tid] = bv; redi[tid] = bi;
        __syncthreads();
        for (int st = 128; st > 0; st >>= 1) {
            if (tid < st) {
                float ov = red[tid + st]; int oi = redi[tid + st];
                if (ov < red[tid] || (ov == red[tid] && oi < redi[tid])) {
                    red[tid] = ov; redi[tid] = oi;
                }
            }
            __syncthreads();
        }
        const int   win = redi[0];
        const float wv  = red[0];
        if (tid == 0) {
            sim_out[b * SEL + sel] = wv;
            g_topk[b * SEL + sel]  = win;
        }
        #pragma unroll
        for (int j = 0; j < 4; j++)
            if (mi[j] == win) mv[j] = CUDART_INF_F;
        __syncthreads();
    }
}

// ============================================================
// Kernel 4: gather selection[b,s] = prompts[topk[b,s]]  (5*768 f32 each)
// One block per (b, s). float4 copies.
// ============================================================
__global__ __launch_bounds__(256)
void gather_kernel(const float* __restrict__ prompts, float* __restrict__ sel_out) {
    const int bs = blockIdx.x;              // 0 .. B*SEL-1
    const int p = g_topk[bs];
    const float4* src = (const float4*)(prompts + (size_t)p * PLEN * DIM);
    float4* dst = (float4*)(sel_out + (size_t)bs * PLEN * DIM);
    const int n4 = PLEN * DIM / 4;          // 960
    for (int i = threadIdx.x; i < n4; i += 256) dst[i] = src[i];
}

// ============================================================
extern "C" void kernel_launch(void* const* d_in, const int* in_sizes, int n_in,
                              void* d_out, int out_size) {
    const float* query  = (const float*)d_in[0];   // [4096, 768]
    const float* key    = (const float*)d_in[1];   // [1024, 768]
    const float* prompts = (const float*)d_in[2];  // [1024, 5, 768]

    float* sim_out = (float*)d_out;                       // [4096, 5]
    float* sel_out = (float*)d_out + (size_t)BATCH * SEL; // [4096, 5, 5, 768]

    knorm_kernel<<<POOL, 128>>>(key);

    dim3 ggrid(POOL / 128, BATCH / 128);   // (8, 32)
    gemm_kernel<<<ggrid, 256>>>(query, key);

    topk_kernel<<<BATCH, 256>>>(query, sim_out);

    gather_kernel<<<BATCH * SEL, 256>>>(prompts, sel_out);
}

// round 5
// speedup vs baseline: 1.4963x; 1.4963x over previous
#include <cuda_runtime.h>
#include <cuda_bf16.h>
#include <math.h>
#include <math_constants.h>
#include <stdint.h>

#define BATCH 4096
#define POOL  1024
#define SEL   5
#define PLEN  5
#define DIM   768
#define KT    (3*DIM)        // 2304 : [hi | lo | hi] x [hi | hi | lo]
#define EPS   1e-8f
#define NCAND 8

// ---------------- scratch (device globals; no allocation allowed) ----------
__device__ __nv_bfloat16 g_A[(size_t)BATCH * KT];   // 18.9 MB
__device__ __nv_bfloat16 g_B[(size_t)POOL  * KT];   // 4.7 MB
__device__ float g_dots[(size_t)BATCH * POOL];      // 16.8 MB
__device__ float g_kn[POOL];
__device__ int   g_topk[BATCH * SEL];

// ---------------- PTX helpers (sm_80-compatible only: no tcgen05) ----------
__device__ __forceinline__ uint32_t smem_u32(const void* p) {
    uint32_t a;
    asm("{ .reg .u64 t; cvta.to.shared.u64 t, %1; cvt.u32.u64 %0, t; }" : "=r"(a) : "l"(p));
    return a;
}
__device__ __forceinline__ void cp_async16(uint32_t saddr, const void* gptr) {
    asm volatile("cp.async.cg.shared.global [%0], [%1], 16;"
                 :: "r"(saddr), "l"(gptr) : "memory");
}
__device__ __forceinline__ void cp_commit() {
    asm volatile("cp.async.commit_group;" ::: "memory");
}
template <int N>
__device__ __forceinline__ void cp_wait() {
    asm volatile("cp.async.wait_group %0;" :: "n"(N) : "memory");
}
__device__ __forceinline__ void ldmatrix_x4(uint32_t* r, uint32_t addr) {
    asm volatile("ldmatrix.sync.aligned.m8n8.x4.shared.b16 {%0,%1,%2,%3}, [%4];"
                 : "=r"(r[0]), "=r"(r[1]), "=r"(r[2]), "=r"(r[3]) : "r"(addr));
}
__device__ __forceinline__ void ldmatrix_x2(uint32_t* r, uint32_t addr) {
    asm volatile("ldmatrix.sync.aligned.m8n8.x2.shared.b16 {%0,%1}, [%2];"
                 : "=r"(r[0]), "=r"(r[1]) : "r"(addr));
}
__device__ __forceinline__ void mma_bf16(float* c, const uint32_t* a, const uint32_t* b) {
    asm volatile(
        "mma.sync.aligned.m16n8k16.row.col.f32.bf16.bf16.f32 "
        "{%0,%1,%2,%3}, {%4,%5,%6,%7}, {%8,%9}, {%0,%1,%2,%3};"
        : "+f"(c[0]), "+f"(c[1]), "+f"(c[2]), "+f"(c[3])
        : "r"(a[0]), "r"(a[1]), "r"(a[2]), "r"(a[3]), "r"(b[0]), "r"(b[1]));
}

// ============================================================
// Conversion: build split-bf16 operands.
// A' row m: [hi(q) | lo(q) | hi(q)], B' row n: [hi(k) | hi(k) | lo(k)]
// ============================================================
__global__ __launch_bounds__(256) void convQ_kernel(const float* __restrict__ q) {
    int idx = blockIdx.x * 256 + threadIdx.x;      // pair index, < BATCH*DIM/2
    float2 f = ((const float2*)q)[idx];
    __nv_bfloat162 h = make_bfloat162(__float2bfloat16(f.x), __float2bfloat16(f.y));
    __nv_bfloat162 l = make_bfloat162(__float2bfloat16(f.x - __bfloat162float(h.x)),
                                      __float2bfloat16(f.y - __bfloat162float(h.y)));
    int m = idx / (DIM / 2), k2 = idx % (DIM / 2);
    __nv_bfloat162* row = (__nv_bfloat162*)(g_A + (size_t)m * KT);
    row[k2] = h;
    row[DIM / 2 + k2] = l;
    row[DIM + k2] = h;
}
__global__ __launch_bounds__(256) void convK_kernel(const float* __restrict__ kp) {
    int idx = blockIdx.x * 256 + threadIdx.x;      // pair index, < POOL*DIM/2
    float2 f = ((const float2*)kp)[idx];
    __nv_bfloat162 h = make_bfloat162(__float2bfloat16(f.x), __float2bfloat16(f.y));
    __nv_bfloat162 l = make_bfloat162(__float2bfloat16(f.x - __bfloat162float(h.x)),
                                      __float2bfloat16(f.y - __bfloat162float(h.y)));
    int n = idx / (DIM / 2), k2 = idx % (DIM / 2);
    __nv_bfloat162* row = (__nv_bfloat162*)(g_B + (size_t)n * KT);
    row[k2] = h;
    row[DIM / 2 + k2] = h;
    row[DIM + k2] = l;
}

// ============================================================
// HMMA bf16 GEMM: dots[4096,1024] = A'[4096,2304] @ B'[1024,2304]^T
// CTA 128x128, BK=64, 3-stage cp.async, 8 warps (warp tile 64x32).
// ============================================================
#define BM 128
#define BN 128
#define BK 64
#define STAGES 3
#define NT (KT / BK)                   // 36
#define A_STAGE_BYTES (BM * BK * 2)    // 16384
#define STAGE_BYTES   (2 * A_STAGE_BYTES)
#define GEMM_SMEM     (STAGES * STAGE_BYTES)   // 98304

__device__ __forceinline__ uint32_t sw_off(int row, int chunk) {
    return (uint32_t)(row * 128 + ((chunk ^ (row & 7)) * 16));
}

__global__ __launch_bounds__(256, 1) void gemm_hmma_kernel() {
    extern __shared__ char smem[];
    const uint32_t sb = smem_u32(smem);
    const int tid = threadIdx.x;
    const int wid = tid >> 5, lid = tid & 31;
    const int bm = blockIdx.y * BM;
    const int bn = blockIdx.x * BN;
    const int wm = (wid >> 2) * 64;
    const int wn = (wid & 3) * 32;

    const __nv_bfloat16* gA = g_A + (size_t)bm * KT;
    const __nv_bfloat16* gB = g_B + (size_t)bn * KT;

    float acc[4][4][4];
    #pragma unroll
    for (int i = 0; i < 4; i++)
        #pragma unroll
        for (int j = 0; j < 4; j++)
            #pragma unroll
            for (int c = 0; c < 4; c++) acc[i][j][c] = 0.f;

    #define LOAD_STAGE(s, t)                                                   \
        {                                                                      \
            uint32_t ab = sb + (s) * STAGE_BYTES;                              \
            uint32_t bb = ab + A_STAGE_BYTES;                                  \
            _Pragma("unroll")                                                  \
            for (int j = 0; j < 4; j++) {                                      \
                int idx = j * 256 + tid;                                       \
                int row = idx >> 3, ch = idx & 7;                              \
                uint32_t so = sw_off(row, ch);                                 \
                cp_async16(ab + so, gA + (size_t)row * KT + (t) * BK + ch * 8);\
                cp_async16(bb + so, gB + (size_t)row * KT + (t) * BK + ch * 8);\
            }                                                                  \
        }

    LOAD_STAGE(0, 0); cp_commit();
    LOAD_STAGE(1, 1); cp_commit();

    for (int t = 0; t < NT; t++) {
        cp_wait<STAGES - 2>();
        __syncthreads();

        int tn = t + STAGES - 1;
        if (tn < NT) LOAD_STAGE(tn % STAGES, tn);
        cp_commit();

        const uint32_t ab = sb + (t % STAGES) * STAGE_BYTES;
        const uint32_t bb = ab + A_STAGE_BYTES;

        #pragma unroll
        for (int k16 = 0; k16 < BK / 16; k16++) {
            uint32_t afr[4][4], bfr[4][2];
            #pragma unroll
            for (int mi = 0; mi < 4; mi++) {
                int r = wm + mi * 16 + (lid & 15);
                int ch = k16 * 2 + (lid >> 4);
                ldmatrix_x4(afr[mi], ab + sw_off(r, ch));
            }
            #pragma unroll
            for (int ni = 0; ni < 4; ni++) {
                int r = wn + ni * 8 + (lid & 7);
                int ch = k16 * 2 + ((lid >> 3) & 1);
                ldmatrix_x2(bfr[ni], bb + sw_off(r, ch));
            }
            #pragma unroll
            for (int mi = 0; mi < 4; mi++)
                #pragma unroll
                for (int ni = 0; ni < 4; ni++)
                    mma_bf16(acc[mi][ni], afr[mi], bfr[ni]);
        }
        __syncthreads();
    }

    const int rbase = bm + wm + (lid >> 2);
    const int cbase = bn + wn + (lid & 3) * 2;
    #pragma unroll
    for (int mi = 0; mi < 4; mi++) {
        #pragma unroll
        for (int ni = 0; ni < 4; ni++) {
            float* p = g_dots + (size_t)(rbase + mi * 16) * POOL + cbase + ni * 8;
            *(float2*)p              = make_float2(acc[mi][ni][0], acc[mi][ni][1]);
            *(float2*)(p + 8 * POOL) = make_float2(acc[mi][ni][2], acc[mi][ni][3]);
        }
    }
}

// ============================================================
// key norms
// ============================================================
__global__ void knorm_kernel(const float* __restrict__ key) {
    const int p = blockIdx.x;
    const float* row = key + (size_t)p * DIM;
    float s = 0.f;
    for (int i = threadIdx.x; i < DIM; i += blockDim.x) {
        float v = row[i];
        s += v * v;
    }
    #pragma unroll
    for (int o = 16; o > 0; o >>= 1) s += __shfl_down_sync(0xFFFFFFFFu, s, o);
    __shared__ float ws[4];
    const int wid = threadIdx.x >> 5, lid = threadIdx.x & 31;
    if (lid == 0) ws[wid] = s;
    __syncthreads();
    if (threadIdx.x == 0) g_kn[p] = sqrtf(ws[0] + ws[1] + ws[2] + ws[3]);
}

// ============================================================
// top-8 candidates from approx dots, then exact fp32 rescore of the
// candidates, final top-5 by (value, index). One block / batch row.
// ============================================================
__global__ __launch_bounds__(256)
void topk_kernel(const float* __restrict__ query, const float* __restrict__ key,
                 float* __restrict__ sim_out) {
    const int b = blockIdx.x;
    const int tid = threadIdx.x;
    const int wid = tid >> 5, lid = tid & 31;

    __shared__ float red[256];
    __shared__ int   redi[256];
    __shared__ float s_qn;
    __shared__ int   s_cand[NCAND];
    __shared__ float s_cval[NCAND];

    // --- query norm (fp32) ---
    float s = 0.f;
    const float* qrow = query + (size_t)b * DIM;
    for (int i = tid; i < DIM; i += 256) {
        float v = qrow[i];
        s += v * v;
    }
    #pragma unroll
    for (int o = 16; o > 0; o >>= 1) s += __shfl_down_sync(0xFFFFFFFFu, s, o);
    if (lid == 0) red[wid] = s;
    __syncthreads();
    if (tid == 0) {
        float t = 0.f;
        for (int w = 0; w < 8; w++) t += red[w];
        s_qn = sqrtf(t);
    }
    __syncthreads();
    const float qn = s_qn;

    // --- approx match values (from bf16 GEMM dots) ---
    float mv[4];
    int   mi[4];
    #pragma unroll
    for (int j = 0; j < 4; j++) {
        int p = tid + j * 256;
        float d = g_dots[(size_t)b * POOL + p];
        float denom = fmaxf(qn * g_kn[p], EPS);
        mv[j] = 1.0f - d / denom;
        mi[j] = p;
    }

    // --- NCAND rounds of block argmin -> candidate set ---
    for (int sel = 0; sel < NCAND; sel++) {
        float bv = mv[0]; int bi = mi[0];
        #pragma unroll
        for (int j = 1; j < 4; j++)
            if (mv[j] < bv || (mv[j] == bv && mi[j] < bi)) { bv = mv[j]; bi = mi[j]; }
        red[tid] = bv; redi[tid] = bi;
        __syncthreads();
        for (int st = 128; st > 0; st >>= 1) {
            if (tid < st) {
                float ov = red[tid + st]; int oi = redi[tid + st];
                if (ov < red[tid] || (ov == red[tid] && oi < redi[tid])) {
                    red[tid] = ov; redi[tid] = oi;
                }
            }
            __syncthreads();
        }
        const int win = redi[0];
        if (tid == 0) s_cand[sel] = win;
        #pragma unroll
        for (int j = 0; j < 4; j++)
            if (mi[j] == win) mv[j] = CUDART_INF_F;
        __syncthreads();
    }

    // --- exact fp32 rescore: warp w handles candidate w ---
    {
        const int c = s_cand[wid];
        const float* krow = key + (size_t)c * DIM;
        float d = 0.f;
        #pragma unroll
        for (int j = 0; j < DIM / 32; j++) {
            int i = lid + j * 32;
            d = fmaf(qrow[i], krow[i], d);
        }
        #pragma unroll
        for (int o = 16; o > 0; o >>= 1) d += __shfl_down_sync(0xFFFFFFFFu, d, o);
        if (lid == 0) {
            float denom = fmaxf(qn * g_kn[c], EPS);
            s_cval[wid] = 1.0f - d / denom;
        }
    }
    __syncthreads();

    // --- final top-5 among 8 rescored candidates (value, then index) ---
    if (tid == 0) {
        float cv[NCAND]; int ci[NCAND];
        #pragma unroll
        for (int j = 0; j < NCAND; j++) { cv[j] = s_cval[j]; ci[j] = s_cand[j]; }
        // insertion sort ascending by (value, index)
        #pragma unroll
        for (int a = 1; a < NCAND; a++) {
            float v = cv[a]; int x = ci[a];
            int p = a - 1;
            while (p >= 0 && (cv[p] > v || (cv[p] == v && ci[p] > x))) {
                cv[p + 1] = cv[p]; ci[p + 1] = ci[p]; p--;
            }
            cv[p + 1] = v; ci[p + 1] = x;
        }
        #pragma unroll
        for (int j = 0; j < SEL; j++) {
            sim_out[b * SEL + j]  = cv[j];
            g_topk[b * SEL + j]   = ci[j];
        }
    }
}

// ============================================================
// gather: selection[b,s] = prompts[topk[b,s]] (streaming stores)
// ============================================================
__global__ __launch_bounds__(256)
void gather_kernel(const float* __restrict__ prompts, float* __restrict__ sel_out) {
    const int bs = blockIdx.x;
    const int p = g_topk[bs];
    const float4* src = (const float4*)(prompts + (size_t)p * PLEN * DIM);
    float4* dst = (float4*)(sel_out + (size_t)bs * PLEN * DIM);
    const int n4 = PLEN * DIM / 4;          // 960
    for (int i = threadIdx.x; i < n4; i += 256) {
        float4 v = src[i];
        __stcs(dst + i, v);
    }
}

// ============================================================
extern "C" void kernel_launch(void* const* d_in, const int* in_sizes, int n_in,
                              void* d_out, int out_size) {
    const float* query   = (const float*)d_in[0];  // [4096, 768]
    const float* key     = (const float*)d_in[1];  // [1024, 768]
    const float* prompts = (const float*)d_in[2];  // [1024, 5, 768]

    float* sim_out = (float*)d_out;                        // [4096, 5]
    float* sel_out = (float*)d_out + (size_t)BATCH * SEL;  // [4096, 5, 5, 768]

    cudaFuncSetAttribute(gemm_hmma_kernel,
                         cudaFuncAttributeMaxDynamicSharedMemorySize, GEMM_SMEM);

    convQ_kernel<<<BATCH * DIM / 512, 256>>>(query);
    convK_kernel<<<POOL * DIM / 512, 256>>>(key);
    knorm_kernel<<<POOL, 128>>>(key);

    dim3 ggrid(POOL / 128, BATCH / 128);   // (8, 32)
    gemm_hmma_kernel<<<ggrid, 256, GEMM_SMEM>>>();

    topk_kernel<<<BATCH, 256>>>(query, key, sim_out);

    gather_kernel<<<BATCH * SEL, 256>>>(prompts, sel_out);
}

// round 6
// speedup vs baseline: 1.7204x; 1.1498x over previous
#include <cuda_runtime.h>
#include <cuda_bf16.h>
#include <math.h>
#include <math_constants.h>
#include <stdint.h>

#define BATCH 4096
#define POOL  1024
#define SEL   5
#define PLEN  5
#define DIM   768
#define KT    (3*DIM)        // 2304 : [hi | lo | hi] x [hi | hi | lo]
#define EPS   1e-8f
#define NCAND 8

// ---------------- scratch (device globals; no allocation allowed) ----------
__device__ __nv_bfloat16 g_A[(size_t)BATCH * KT];   // 18.9 MB
__device__ __nv_bfloat16 g_B[(size_t)POOL  * KT];   // 4.7 MB
__device__ float g_dots[(size_t)BATCH * POOL];      // 16.8 MB
__device__ float g_kn[POOL];
__device__ int   g_topk[BATCH * SEL];

// ---------------- PTX helpers (sm_80-compatible only: no tcgen05) ----------
__device__ __forceinline__ uint32_t smem_u32(const void* p) {
    uint32_t a;
    asm("{ .reg .u64 t; cvta.to.shared.u64 t, %1; cvt.u32.u64 %0, t; }" : "=r"(a) : "l"(p));
    return a;
}
__device__ __forceinline__ void cp_async16(uint32_t saddr, const void* gptr) {
    asm volatile("cp.async.cg.shared.global [%0], [%1], 16;"
                 :: "r"(saddr), "l"(gptr) : "memory");
}
__device__ __forceinline__ void cp_commit() {
    asm volatile("cp.async.commit_group;" ::: "memory");
}
template <int N>
__device__ __forceinline__ void cp_wait() {
    asm volatile("cp.async.wait_group %0;" :: "n"(N) : "memory");
}
__device__ __forceinline__ void ldmatrix_x4(uint32_t* r, uint32_t addr) {
    asm volatile("ldmatrix.sync.aligned.m8n8.x4.shared.b16 {%0,%1,%2,%3}, [%4];"
                 : "=r"(r[0]), "=r"(r[1]), "=r"(r[2]), "=r"(r[3]) : "r"(addr));
}
__device__ __forceinline__ void ldmatrix_x2(uint32_t* r, uint32_t addr) {
    asm volatile("ldmatrix.sync.aligned.m8n8.x2.shared.b16 {%0,%1}, [%2];"
                 : "=r"(r[0]), "=r"(r[1]) : "r"(addr));
}
__device__ __forceinline__ void mma_bf16(float* c, const uint32_t* a, const uint32_t* b) {
    asm volatile(
        "mma.sync.aligned.m16n8k16.row.col.f32.bf16.bf16.f32 "
        "{%0,%1,%2,%3}, {%4,%5,%6,%7}, {%8,%9}, {%0,%1,%2,%3};"
        : "+f"(c[0]), "+f"(c[1]), "+f"(c[2]), "+f"(c[3])
        : "r"(a[0]), "r"(a[1]), "r"(a[2]), "r"(a[3]), "r"(b[0]), "r"(b[1]));
}

// ============================================================
// Fused conversion: build split-bf16 operands for Q and K.
// A' row m: [hi(q) | lo(q) | hi(q)], B' row n: [hi(k) | hi(k) | lo(k)]
// ============================================================
#define QBLKS (BATCH * DIM / 512)      // 6144
#define KBLKS (POOL  * DIM / 512)      // 1536
__global__ __launch_bounds__(256) void conv_kernel(const float* __restrict__ q,
                                                   const float* __restrict__ kp) {
    int bid = blockIdx.x;
    if (bid < QBLKS) {
        int idx = bid * 256 + threadIdx.x;
        float2 f = ((const float2*)q)[idx];
        __nv_bfloat162 h = make_bfloat162(__float2bfloat16(f.x), __float2bfloat16(f.y));
        __nv_bfloat162 l = make_bfloat162(__float2bfloat16(f.x - __bfloat162float(h.x)),
                                          __float2bfloat16(f.y - __bfloat162float(h.y)));
        int m = idx / (DIM / 2), k2 = idx % (DIM / 2);
        __nv_bfloat162* row = (__nv_bfloat162*)(g_A + (size_t)m * KT);
        row[k2] = h;
        row[DIM / 2 + k2] = l;
        row[DIM + k2] = h;
    } else {
        int idx = (bid - QBLKS) * 256 + threadIdx.x;
        float2 f = ((const float2*)kp)[idx];
        __nv_bfloat162 h = make_bfloat162(__float2bfloat16(f.x), __float2bfloat16(f.y));
        __nv_bfloat162 l = make_bfloat162(__float2bfloat16(f.x - __bfloat162float(h.x)),
                                          __float2bfloat16(f.y - __bfloat162float(h.y)));
        int n = idx / (DIM / 2), k2 = idx % (DIM / 2);
        __nv_bfloat162* row = (__nv_bfloat162*)(g_B + (size_t)n * KT);
        row[k2] = h;
        row[DIM / 2 + k2] = h;
        row[DIM + k2] = l;
    }
}

// ============================================================
// HMMA bf16 GEMM: dots[4096,1024] = A'[4096,2304] @ B'[1024,2304]^T
// CTA 128x128, BK=64, 3-stage cp.async, 8 warps (warp tile 64x32).
// __launch_bounds__(256,2): 2 CTAs/SM -> all 256 CTAs resident.
// ============================================================
#define BM 128
#define BN 128
#define BK 64
#define STAGES 3
#define NT (KT / BK)                   // 36
#define A_STAGE_BYTES (BM * BK * 2)    // 16384
#define STAGE_BYTES   (2 * A_STAGE_BYTES)
#define GEMM_SMEM     (STAGES * STAGE_BYTES)   // 98304

__device__ __forceinline__ uint32_t sw_off(int row, int chunk) {
    return (uint32_t)(row * 128 + ((chunk ^ (row & 7)) * 16));
}

__global__ __launch_bounds__(256, 2) void gemm_hmma_kernel() {
    extern __shared__ char smem[];
    const uint32_t sb = smem_u32(smem);
    const int tid = threadIdx.x;
    const int wid = tid >> 5, lid = tid & 31;
    const int bm = blockIdx.y * BM;
    const int bn = blockIdx.x * BN;
    const int wm = (wid >> 2) * 64;
    const int wn = (wid & 3) * 32;

    float acc[4][4][4];
    #pragma unroll
    for (int i = 0; i < 4; i++)
        #pragma unroll
        for (int j = 0; j < 4; j++)
            #pragma unroll
            for (int c = 0; c < 4; c++) acc[i][j][c] = 0.f;

    // hoisted per-thread load addressing (advance pointers by BK per k-tile)
    uint32_t soff[4];
    const __nv_bfloat16 *pa[4], *pb[4];
    {
        const __nv_bfloat16* gA = g_A + (size_t)bm * KT;
        const __nv_bfloat16* gB = g_B + (size_t)bn * KT;
        #pragma unroll
        for (int j = 0; j < 4; j++) {
            int idx = j * 256 + tid;
            int row = idx >> 3, ch = idx & 7;
            soff[j] = sw_off(row, ch);
            pa[j] = gA + (size_t)row * KT + ch * 8;
            pb[j] = gB + (size_t)row * KT + ch * 8;
        }
    }

    #define LOAD_STAGE(s, t)                                                   \
        {                                                                      \
            uint32_t ab = sb + (s) * STAGE_BYTES;                              \
            uint32_t bb = ab + A_STAGE_BYTES;                                  \
            _Pragma("unroll")                                                  \
            for (int j = 0; j < 4; j++) {                                      \
                cp_async16(ab + soff[j], pa[j] + (t) * BK);                    \
                cp_async16(bb + soff[j], pb[j] + (t) * BK);                    \
            }                                                                  \
        }

    LOAD_STAGE(0, 0); cp_commit();
    LOAD_STAGE(1, 1); cp_commit();

    // per-warp ldmatrix base offsets (constant across tiles)
    const int ar0 = wm + (lid & 15);
    const int ach = (lid >> 4);
    const int br0 = wn + (lid & 7);
    const int bch = ((lid >> 3) & 1);

    for (int t = 0; t < NT; t++) {
        cp_wait<STAGES - 2>();
        __syncthreads();

        int tn = t + STAGES - 1;
        if (tn < NT) LOAD_STAGE(tn % STAGES, tn);
        cp_commit();

        const uint32_t ab = sb + (t % STAGES) * STAGE_BYTES;
        const uint32_t bb = ab + A_STAGE_BYTES;

        #pragma unroll
        for (int k16 = 0; k16 < BK / 16; k16++) {
            uint32_t afr[4][4], bfr[4][2];
            #pragma unroll
            for (int mi = 0; mi < 4; mi++)
                ldmatrix_x4(afr[mi], ab + sw_off(ar0 + mi * 16, k16 * 2 + ach));
            #pragma unroll
            for (int ni = 0; ni < 4; ni++)
                ldmatrix_x2(bfr[ni], bb + sw_off(br0 + ni * 8, k16 * 2 + bch));
            #pragma unroll
            for (int mi = 0; mi < 4; mi++)
                #pragma unroll
                for (int ni = 0; ni < 4; ni++)
                    mma_bf16(acc[mi][ni], afr[mi], bfr[ni]);
        }
        __syncthreads();
    }

    const int rbase = bm + wm + (lid >> 2);
    const int cbase = bn + wn + (lid & 3) * 2;
    #pragma unroll
    for (int mi = 0; mi < 4; mi++) {
        #pragma unroll
        for (int ni = 0; ni < 4; ni++) {
            float* p = g_dots + (size_t)(rbase + mi * 16) * POOL + cbase + ni * 8;
            *(float2*)p              = make_float2(acc[mi][ni][0], acc[mi][ni][1]);
            *(float2*)(p + 8 * POOL) = make_float2(acc[mi][ni][2], acc[mi][ni][3]);
        }
    }
}

// ============================================================
// key norms
// ============================================================
__global__ void knorm_kernel(const float* __restrict__ key) {
    const int p = blockIdx.x;
    const float* row = key + (size_t)p * DIM;
    float s = 0.f;
    for (int i = threadIdx.x; i < DIM; i += blockDim.x) {
        float v = row[i];
        s += v * v;
    }
    #pragma unroll
    for (int o = 16; o > 0; o >>= 1) s += __shfl_down_sync(0xFFFFFFFFu, s, o);
    __shared__ float ws[4];
    const int wid = threadIdx.x >> 5, lid = threadIdx.x & 31;
    if (lid == 0) ws[wid] = s;
    __syncthreads();
    if (threadIdx.x == 0) g_kn[p] = sqrtf(ws[0] + ws[1] + ws[2] + ws[3]);
}

// ============================================================
// top-8 candidates from approx dots (warp-shuffle argmin), exact fp32
// rescore, final top-5 by (value, index). One block / batch row.
// ============================================================
__device__ __forceinline__ void amin2(float& v, int& i, float ov, int oi) {
    if (ov < v || (ov == v && oi < i)) { v = ov; i = oi; }
}

__global__ __launch_bounds__(256)
void topk_kernel(const float* __restrict__ query, const float* __restrict__ key,
                 float* __restrict__ sim_out) {
    const int b = blockIdx.x;
    const int tid = threadIdx.x;
    const int wid = tid >> 5, lid = tid & 31;

    __shared__ float wval[8];
    __shared__ int   widx[8];
    __shared__ float s_qn;
    __shared__ int   s_win;
    __shared__ int   s_cand[NCAND];
    __shared__ float s_cval[NCAND];

    // --- query norm (fp32) ---
    float s = 0.f;
    const float* qrow = query + (size_t)b * DIM;
    for (int i = tid; i < DIM; i += 256) {
        float v = qrow[i];
        s += v * v;
    }
    #pragma unroll
    for (int o = 16; o > 0; o >>= 1) s += __shfl_down_sync(0xFFFFFFFFu, s, o);
    if (lid == 0) wval[wid] = s;
    __syncthreads();
    if (tid == 0) {
        float t = 0.f;
        for (int w = 0; w < 8; w++) t += wval[w];
        s_qn = sqrtf(t);
    }
    __syncthreads();
    const float qn = s_qn;

    // --- approx match values (from bf16 GEMM dots) ---
    float mv[4];
    int   mi[4];
    #pragma unroll
    for (int j = 0; j < 4; j++) {
        int p = tid + j * 256;
        float d = g_dots[(size_t)b * POOL + p];
        float denom = fmaxf(qn * g_kn[p], EPS);
        mv[j] = 1.0f - d / denom;
        mi[j] = p;
    }

    // --- NCAND rounds of block argmin (warp shuffles, 2 barriers/round) ---
    for (int sel = 0; sel < NCAND; sel++) {
        float bv = mv[0]; int bi = mi[0];
        #pragma unroll
        for (int j = 1; j < 4; j++) amin2(bv, bi, mv[j], mi[j]);
        #pragma unroll
        for (int o = 16; o > 0; o >>= 1) {
            float ov = __shfl_down_sync(0xFFFFFFFFu, bv, o);
            int   oi = __shfl_down_sync(0xFFFFFFFFu, bi, o);
            amin2(bv, bi, ov, oi);
        }
        if (lid == 0) { wval[wid] = bv; widx[wid] = bi; }
        __syncthreads();
        if (wid == 0) {
            float fv = (lid < 8) ? wval[lid] : CUDART_INF_F;
            int   fi = (lid < 8) ? widx[lid] : 0x7FFFFFFF;
            #pragma unroll
            for (int o = 4; o > 0; o >>= 1) {
                float ov = __shfl_down_sync(0xFFFFFFFFu, fv, o);
                int   oi = __shfl_down_sync(0xFFFFFFFFu, fi, o);
                amin2(fv, fi, ov, oi);
            }
            if (lid == 0) { s_win = fi; s_cand[sel] = fi; }
        }
        __syncthreads();
        const int win = s_win;
        #pragma unroll
        for (int j = 0; j < 4; j++)
            if (mi[j] == win) mv[j] = CUDART_INF_F;
    }

    // --- exact fp32 rescore: warp w handles candidate w ---
    {
        const int c = s_cand[wid];
        const float* krow = key + (size_t)c * DIM;
        float d = 0.f;
        #pragma unroll
        for (int j = 0; j < DIM / 32; j++) {
            int i = lid + j * 32;
            d = fmaf(qrow[i], krow[i], d);
        }
        #pragma unroll
        for (int o = 16; o > 0; o >>= 1) d += __shfl_down_sync(0xFFFFFFFFu, d, o);
        if (lid == 0) {
            float denom = fmaxf(qn * g_kn[c], EPS);
            s_cval[wid] = 1.0f - d / denom;
        }
    }
    __syncthreads();

    // --- final top-5 among 8 rescored candidates (value, then index) ---
    if (tid == 0) {
        float cv[NCAND]; int ci[NCAND];
        #pragma unroll
        for (int j = 0; j < NCAND; j++) { cv[j] = s_cval[j]; ci[j] = s_cand[j]; }
        #pragma unroll
        for (int a = 1; a < NCAND; a++) {
            float v = cv[a]; int x = ci[a];
            int p = a - 1;
            while (p >= 0 && (cv[p] > v || (cv[p] == v && ci[p] > x))) {
                cv[p + 1] = cv[p]; ci[p + 1] = ci[p]; p--;
            }
            cv[p + 1] = v; ci[p + 1] = x;
        }
        #pragma unroll
        for (int j = 0; j < SEL; j++) {
            sim_out[b * SEL + j] = cv[j];
            g_topk[b * SEL + j]  = ci[j];
        }
    }
}

// ============================================================
// gather: selection[b,s] = prompts[topk[b,s]] (streaming stores)
// ============================================================
__global__ __launch_bounds__(256)
void gather_kernel(const float* __restrict__ prompts, float* __restrict__ sel_out) {
    const int bs = blockIdx.x;
    const int p = g_topk[bs];
    const float4* src = (const float4*)(prompts + (size_t)p * PLEN * DIM);
    float4* dst = (float4*)(sel_out + (size_t)bs * PLEN * DIM);
    const int n4 = PLEN * DIM / 4;          // 960
    for (int i = threadIdx.x; i < n4; i += 256) {
        float4 v = src[i];
        __stcs(dst + i, v);
    }
}

// ============================================================
extern "C" void kernel_launch(void* const* d_in, const int* in_sizes, int n_in,
                              void* d_out, int out_size) {
    const float* query   = (const float*)d_in[0];  // [4096, 768]
    const float* key     = (const float*)d_in[1];  // [1024, 768]
    const float* prompts = (const float*)d_in[2];  // [1024, 5, 768]

    float* sim_out = (float*)d_out;                        // [4096, 5]
    float* sel_out = (float*)d_out + (size_t)BATCH * SEL;  // [4096, 5, 5, 768]

    cudaFuncSetAttribute(gemm_hmma_kernel,
                         cudaFuncAttributeMaxDynamicSharedMemorySize, GEMM_SMEM);

    conv_kernel<<<QBLKS + KBLKS, 256>>>(query, key);
    knorm_kernel<<<POOL, 128>>>(key);

    dim3 ggrid(POOL / 128, BATCH / 128);   // (8, 32)
    gemm_hmma_kernel<<<ggrid, 256, GEMM_SMEM>>>();

    topk_kernel<<<BATCH, 256>>>(query, key, sim_out);

    gather_kernel<<<BATCH * SEL, 256>>>(prompts, sel_out);
}

// round 7
// speedup vs baseline: 1.7715x; 1.0297x over previous
#include <cuda_runtime.h>
#include <cuda_bf16.h>
#include <math.h>
#include <math_constants.h>
#include <stdint.h>

#define BATCH 4096
#define POOL  1024
#define SEL   5
#define PLEN  5
#define DIM   768
#define KT    (3*DIM)        // 2304 : [hi | lo | hi] x [hi | hi | lo]
#define EPS   1e-8f
#define NCAND 8

// ---------------- scratch (device globals; no allocation allowed) ----------
__device__ __nv_bfloat16 g_A[(size_t)BATCH * KT];   // 18.9 MB
__device__ __nv_bfloat16 g_B[(size_t)POOL  * KT];   // 4.7 MB
__device__ float g_dots[(size_t)BATCH * POOL];      // 16.8 MB
__device__ float g_kn[POOL];

// ---------------- PTX helpers (sm_80-compatible only: no tcgen05) ----------
__device__ __forceinline__ uint32_t smem_u32(const void* p) {
    uint32_t a;
    asm("{ .reg .u64 t; cvta.to.shared.u64 t, %1; cvt.u32.u64 %0, t; }" : "=r"(a) : "l"(p));
    return a;
}
__device__ __forceinline__ void cp_async16(uint32_t saddr, const void* gptr) {
    asm volatile("cp.async.cg.shared.global [%0], [%1], 16;"
                 :: "r"(saddr), "l"(gptr) : "memory");
}
__device__ __forceinline__ void cp_commit() {
    asm volatile("cp.async.commit_group;" ::: "memory");
}
template <int N>
__device__ __forceinline__ void cp_wait() {
    asm volatile("cp.async.wait_group %0;" :: "n"(N) : "memory");
}
__device__ __forceinline__ void ldmatrix_x4(uint32_t* r, uint32_t addr) {
    asm volatile("ldmatrix.sync.aligned.m8n8.x4.shared.b16 {%0,%1,%2,%3}, [%4];"
                 : "=r"(r[0]), "=r"(r[1]), "=r"(r[2]), "=r"(r[3]) : "r"(addr));
}
__device__ __forceinline__ void ldmatrix_x2(uint32_t* r, uint32_t addr) {
    asm volatile("ldmatrix.sync.aligned.m8n8.x2.shared.b16 {%0,%1}, [%2];"
                 : "=r"(r[0]), "=r"(r[1]) : "r"(addr));
}
__device__ __forceinline__ void mma_bf16(float* c, const uint32_t* a, const uint32_t* b) {
    asm volatile(
        "mma.sync.aligned.m16n8k16.row.col.f32.bf16.bf16.f32 "
        "{%0,%1,%2,%3}, {%4,%5,%6,%7}, {%8,%9}, {%0,%1,%2,%3};"
        : "+f"(c[0]), "+f"(c[1]), "+f"(c[2]), "+f"(c[3])
        : "r"(a[0]), "r"(a[1]), "r"(a[2]), "r"(a[3]), "r"(b[0]), "r"(b[1]));
}

// orderable-uint encoding of float (monotonic: a<b  <=>  enc(a)<enc(b))
__device__ __forceinline__ uint32_t ford(float f) {
    uint32_t u = __float_as_uint(f);
    return u ^ (((int32_t)u >> 31) | 0x80000000u);
}

// ============================================================
// Fused conversion: build split-bf16 operands for Q and K.
// A' row m: [hi(q) | lo(q) | hi(q)], B' row n: [hi(k) | hi(k) | lo(k)]
// ============================================================
#define QBLKS (BATCH * DIM / 512)      // 6144
#define KBLKS (POOL  * DIM / 512)      // 1536
__global__ __launch_bounds__(256) void conv_kernel(const float* __restrict__ q,
                                                   const float* __restrict__ kp) {
    int bid = blockIdx.x;
    if (bid < QBLKS) {
        int idx = bid * 256 + threadIdx.x;
        float2 f = ((const float2*)q)[idx];
        __nv_bfloat162 h = make_bfloat162(__float2bfloat16(f.x), __float2bfloat16(f.y));
        __nv_bfloat162 l = make_bfloat162(__float2bfloat16(f.x - __bfloat162float(h.x)),
                                          __float2bfloat16(f.y - __bfloat162float(h.y)));
        int m = idx / (DIM / 2), k2 = idx % (DIM / 2);
        __nv_bfloat162* row = (__nv_bfloat162*)(g_A + (size_t)m * KT);
        row[k2] = h;
        row[DIM / 2 + k2] = l;
        row[DIM + k2] = h;
    } else {
        int idx = (bid - QBLKS) * 256 + threadIdx.x;
        float2 f = ((const float2*)kp)[idx];
        __nv_bfloat162 h = make_bfloat162(__float2bfloat16(f.x), __float2bfloat16(f.y));
        __nv_bfloat162 l = make_bfloat162(__float2bfloat16(f.x - __bfloat162float(h.x)),
                                          __float2bfloat16(f.y - __bfloat162float(h.y)));
        int n = idx / (DIM / 2), k2 = idx % (DIM / 2);
        __nv_bfloat162* row = (__nv_bfloat162*)(g_B + (size_t)n * KT);
        row[k2] = h;
        row[DIM / 2 + k2] = h;
        row[DIM + k2] = l;
    }
}

// ============================================================
// HMMA bf16 GEMM: dots[4096,1024] = A'[4096,2304] @ B'[1024,2304]^T
// ============================================================
#define BM 128
#define BN 128
#define BK 64
#define STAGES 3
#define NT (KT / BK)                   // 36
#define A_STAGE_BYTES (BM * BK * 2)    // 16384
#define STAGE_BYTES   (2 * A_STAGE_BYTES)
#define GEMM_SMEM     (STAGES * STAGE_BYTES)   // 98304

__device__ __forceinline__ uint32_t sw_off(int row, int chunk) {
    return (uint32_t)(row * 128 + ((chunk ^ (row & 7)) * 16));
}

__global__ __launch_bounds__(256, 2) void gemm_hmma_kernel() {
    extern __shared__ char smem[];
    const uint32_t sb = smem_u32(smem);
    const int tid = threadIdx.x;
    const int wid = tid >> 5, lid = tid & 31;
    const int bm = blockIdx.y * BM;
    const int bn = blockIdx.x * BN;
    const int wm = (wid >> 2) * 64;
    const int wn = (wid & 3) * 32;

    float acc[4][4][4];
    #pragma unroll
    for (int i = 0; i < 4; i++)
        #pragma unroll
        for (int j = 0; j < 4; j++)
            #pragma unroll
            for (int c = 0; c < 4; c++) acc[i][j][c] = 0.f;

    uint32_t soff[4];
    const __nv_bfloat16 *pa[4], *pb[4];
    {
        const __nv_bfloat16* gA = g_A + (size_t)bm * KT;
        const __nv_bfloat16* gB = g_B + (size_t)bn * KT;
        #pragma unroll
        for (int j = 0; j < 4; j++) {
            int idx = j * 256 + tid;
            int row = idx >> 3, ch = idx & 7;
            soff[j] = sw_off(row, ch);
            pa[j] = gA + (size_t)row * KT + ch * 8;
            pb[j] = gB + (size_t)row * KT + ch * 8;
        }
    }

    #define LOAD_STAGE(s, t)                                                   \
        {                                                                      \
            uint32_t ab = sb + (s) * STAGE_BYTES;                              \
            uint32_t bb = ab + A_STAGE_BYTES;                                  \
            _Pragma("unroll")                                                  \
            for (int j = 0; j < 4; j++) {                                      \
                cp_async16(ab + soff[j], pa[j] + (t) * BK);                    \
                cp_async16(bb + soff[j], pb[j] + (t) * BK);                    \
            }                                                                  \
        }

    LOAD_STAGE(0, 0); cp_commit();
    LOAD_STAGE(1, 1); cp_commit();

    const int ar0 = wm + (lid & 15);
    const int ach = (lid >> 4);
    const int br0 = wn + (lid & 7);
    const int bch = ((lid >> 3) & 1);

    for (int t = 0; t < NT; t++) {
        cp_wait<STAGES - 2>();
        __syncthreads();

        int tn = t + STAGES - 1;
        if (tn < NT) LOAD_STAGE(tn % STAGES, tn);
        cp_commit();

        const uint32_t ab = sb + (t % STAGES) * STAGE_BYTES;
        const uint32_t bb = ab + A_STAGE_BYTES;

        #pragma unroll
        for (int k16 = 0; k16 < BK / 16; k16++) {
            uint32_t afr[4][4], bfr[4][2];
            #pragma unroll
            for (int mi = 0; mi < 4; mi++)
                ldmatrix_x4(afr[mi], ab + sw_off(ar0 + mi * 16, k16 * 2 + ach));
            #pragma unroll
            for (int ni = 0; ni < 4; ni++)
                ldmatrix_x2(bfr[ni], bb + sw_off(br0 + ni * 8, k16 * 2 + bch));
            #pragma unroll
            for (int mi = 0; mi < 4; mi++)
                #pragma unroll
                for (int ni = 0; ni < 4; ni++)
                    mma_bf16(acc[mi][ni], afr[mi], bfr[ni]);
        }
        __syncthreads();
    }

    const int rbase = bm + wm + (lid >> 2);
    const int cbase = bn + wn + (lid & 3) * 2;
    #pragma unroll
    for (int mi = 0; mi < 4; mi++) {
        #pragma unroll
        for (int ni = 0; ni < 4; ni++) {
            float* p = g_dots + (size_t)(rbase + mi * 16) * POOL + cbase + ni * 8;
            *(float2*)p              = make_float2(acc[mi][ni][0], acc[mi][ni][1]);
            *(float2*)(p + 8 * POOL) = make_float2(acc[mi][ni][2], acc[mi][ni][3]);
        }
    }
}

// ============================================================
// key norms
// ============================================================
__global__ void knorm_kernel(const float* __restrict__ key) {
    const int p = blockIdx.x;
    const float* row = key + (size_t)p * DIM;
    float s = 0.f;
    for (int i = threadIdx.x; i < DIM; i += blockDim.x) {
        float v = row[i];
        s += v * v;
    }
    #pragma unroll
    for (int o = 16; o > 0; o >>= 1) s += __shfl_down_sync(0xFFFFFFFFu, s, o);
    __shared__ float ws[4];
    const int wid = threadIdx.x >> 5, lid = threadIdx.x & 31;
    if (lid == 0) ws[wid] = s;
    __syncthreads();
    if (threadIdx.x == 0) g_kn[p] = sqrtf(ws[0] + ws[1] + ws[2] + ws[3]);
}

// ============================================================
// FUSED: per-row top-8 candidates (u64 packed, warp-local extraction),
// exact fp32 rescore, final top-5, then gather of the 5 prompts.
// One block (256 threads) per batch row.
// ============================================================
__global__ __launch_bounds__(256)
void topk_gather_kernel(const float* __restrict__ query, const float* __restrict__ key,
                        const float* __restrict__ prompts,
                        float* __restrict__ sim_out, float* __restrict__ sel_out) {
    const int b = blockIdx.x;
    const int tid = threadIdx.x;
    const int wid = tid >> 5, lid = tid & 31;

    __shared__ float wred[8];
    __shared__ float s_qn;
    __shared__ unsigned long long s_c64[64];   // 8 warps x 8 candidates
    __shared__ int   s_top[NCAND];
    __shared__ float s_cval[NCAND];
    __shared__ int   s_sel[SEL];

    // --- query norm (fp32) ---
    float s = 0.f;
    const float* qrow = query + (size_t)b * DIM;
    for (int i = tid; i < DIM; i += 256) {
        float v = qrow[i];
        s += v * v;
    }
    #pragma unroll
    for (int o = 16; o > 0; o >>= 1) s += __shfl_down_sync(0xFFFFFFFFu, s, o);
    if (lid == 0) wred[wid] = s;
    __syncthreads();
    if (tid == 0) {
        float t = 0.f;
        for (int w = 0; w < 8; w++) t += wred[w];
        s_qn = sqrtf(t);
    }
    __syncthreads();
    const float qn = s_qn;

    // --- approx match values packed as (orderable(value) << 32) | index ---
    unsigned long long v64[4];
    #pragma unroll
    for (int j = 0; j < 4; j++) {
        int p = tid + j * 256;
        float d = g_dots[(size_t)b * POOL + p];
        float denom = fmaxf(qn * g_kn[p], EPS);
        float m = 1.0f - d / denom;
        v64[j] = ((unsigned long long)ford(m) << 32) | (uint32_t)p;
    }

    // --- warp-local top-8 extraction (no block barriers) ---
    #pragma unroll
    for (int r = 0; r < NCAND; r++) {
        unsigned long long m = v64[0];
        #pragma unroll
        for (int j = 1; j < 4; j++) m = min(m, v64[j]);
        #pragma unroll
        for (int o = 16; o > 0; o >>= 1)
            m = min(m, __shfl_xor_sync(0xFFFFFFFFu, m, o));
        if (lid == 0) s_c64[wid * 8 + r] = m;
        #pragma unroll
        for (int j = 0; j < 4; j++)
            if (v64[j] == m) v64[j] = 0xFFFFFFFFFFFFFFFFull;
    }
    __syncthreads();

    // --- warp 0 merges 64 -> top-8 ---
    if (wid == 0) {
        unsigned long long a = s_c64[lid];
        unsigned long long c = s_c64[lid + 32];
        #pragma unroll
        for (int r = 0; r < NCAND; r++) {
            unsigned long long m = min(a, c);
            #pragma unroll
            for (int o = 16; o > 0; o >>= 1)
                m = min(m, __shfl_xor_sync(0xFFFFFFFFu, m, o));
            if (lid == 0) s_top[r] = (int)(uint32_t)m;
            if (a == m) a = 0xFFFFFFFFFFFFFFFFull;
            if (c == m) c = 0xFFFFFFFFFFFFFFFFull;
        }
    }
    __syncthreads();

    // --- exact fp32 rescore: warp w handles candidate w ---
    {
        const int c = s_top[wid];
        const float* krow = key + (size_t)c * DIM;
        float d = 0.f;
        #pragma unroll
        for (int j = 0; j < DIM / 32; j++) {
            int i = lid + j * 32;
            d = fmaf(qrow[i], krow[i], d);
        }
        #pragma unroll
        for (int o = 16; o > 0; o >>= 1) d += __shfl_down_sync(0xFFFFFFFFu, d, o);
        if (lid == 0) {
            float denom = fmaxf(qn * g_kn[c], EPS);
            s_cval[wid] = 1.0f - d / denom;
        }
    }
    __syncthreads();

    // --- final top-5 among 8 rescored candidates (value, then index) ---
    if (tid == 0) {
        float cv[NCAND]; int ci[NCAND];
        #pragma unroll
        for (int j = 0; j < NCAND; j++) { cv[j] = s_cval[j]; ci[j] = s_top[j]; }
        #pragma unroll
        for (int a = 1; a < NCAND; a++) {
            float v = cv[a]; int x = ci[a];
            int p = a - 1;
            while (p >= 0 && (cv[p] > v || (cv[p] == v && ci[p] > x))) {
                cv[p + 1] = cv[p]; ci[p + 1] = ci[p]; p--;
            }
            cv[p + 1] = v; ci[p + 1] = x;
        }
        #pragma unroll
        for (int j = 0; j < SEL; j++) {
            sim_out[b * SEL + j] = cv[j];
            s_sel[j] = ci[j];
        }
    }
    __syncthreads();

    // --- gather: copy 5 selected prompts (5*768 f32 each), streaming stores ---
    #pragma unroll
    for (int sidx = 0; sidx < SEL; sidx++) {
        const int p = s_sel[sidx];
        const float4* src = (const float4*)(prompts + (size_t)p * PLEN * DIM);
        float4* dst = (float4*)(sel_out + ((size_t)b * SEL + sidx) * PLEN * DIM);
        for (int i = tid; i < PLEN * DIM / 4; i += 256) {
            float4 v = __ldg(src + i);
            __stcs(dst + i, v);
        }
    }
}

// ============================================================
extern "C" void kernel_launch(void* const* d_in, const int* in_sizes, int n_in,
                              void* d_out, int out_size) {
    const float* query   = (const float*)d_in[0];  // [4096, 768]
    const float* key     = (const float*)d_in[1];  // [1024, 768]
    const float* prompts = (const float*)d_in[2];  // [1024, 5, 768]

    float* sim_out = (float*)d_out;                        // [4096, 5]
    float* sel_out = (float*)d_out + (size_t)BATCH * SEL;  // [4096, 5, 5, 768]

    cudaFuncSetAttribute(gemm_hmma_kernel,
                         cudaFuncAttributeMaxDynamicSharedMemorySize, GEMM_SMEM);

    conv_kernel<<<QBLKS + KBLKS, 256>>>(query, key);
    knorm_kernel<<<POOL, 128>>>(key);

    dim3 ggrid(POOL / 128, BATCH / 128);   // (8, 32)
    gemm_hmma_kernel<<<ggrid, 256, GEMM_SMEM>>>();

    topk_gather_kernel<<<BATCH, 256>>>(query, key, prompts, sim_out, sel_out);
}